// round 10
// baseline (speedup 1.0000x reference)
#include <cuda_runtime.h>
#include <cuda_fp16.h>
#include <mma.h>
using namespace nvcuda;

#define NN 100000
#define EE 1600000
#define GG 256
#define NBLK 98   // ceil(NN/1024) for scan
#define SPLIT 50048  // node split for rgcn1/xw2 pipeline (multiple of 64 and 8)

// ---------------- scratch (__device__ globals, allocation-free) ----------------
__device__ __half g_hh[NN * 128];     // GAT transformed features (fp16)
__device__ float g_asrc[NN * 4];
__device__ float g_adst[NN * 4];
__device__ __half g_xh_hi[NN * 64];   // x split hi
__device__ __half g_xh_lo[NN * 64];   // x split lo
__device__ __half g_w1h[64 * 288];    // packed rgcn1 weights hi
__device__ __half g_w1l[64 * 288];    // packed rgcn1 weights lo
__device__ __half g_whh[64 * 144];    // gat_w + att cols, hi (cols 136..143 zero)
__device__ __half g_whl[64 * 144];    // gat_w + att cols, lo
__device__ float g_w2[32 * 144];      // packed [k][r*16+c | root 128..143] (fp32)
__device__ __half g_xw1[NN * 288];    // fp16
__device__ float g_z1[NN * 32];
__device__ __half g_xw2[NN * 144];    // fp16
__device__ float g_gmax[GG * 16];
__device__ float g_gsum[GG * 16];
__device__ float g_npg[GG];
// CSR
__device__ int g_deg[NN];
__device__ int g_off[NN];
__device__ int g_cur[NN];
__device__ int g_scan[NBLK * 1024];
__device__ int g_bsum[NBLK];
__device__ int g_bpre[NBLK];
__device__ int g_csr[EE];             // src | (rel<<20)

// ---------------- persistent streams/events (host-side objects only) ----------------
struct ForkCtx {
    cudaStream_t s2, s3;
    cudaEvent_t evStart, evCSR, evR1, evX2lo, evGat, evCvt, evPack;
    ForkCtx() {
        cudaStreamCreateWithFlags(&s2, cudaStreamNonBlocking);
        cudaStreamCreateWithFlags(&s3, cudaStreamNonBlocking);
        cudaEventCreateWithFlags(&evStart, cudaEventDisableTiming);
        cudaEventCreateWithFlags(&evCSR, cudaEventDisableTiming);
        cudaEventCreateWithFlags(&evR1, cudaEventDisableTiming);
        cudaEventCreateWithFlags(&evX2lo, cudaEventDisableTiming);
        cudaEventCreateWithFlags(&evGat, cudaEventDisableTiming);
        cudaEventCreateWithFlags(&evCvt, cudaEventDisableTiming);
        cudaEventCreateWithFlags(&evPack, cudaEventDisableTiming);
    }
};
static ForkCtx g_fork;

// ---------------- helpers ----------------
__device__ __forceinline__ float lrelu(float x, float s) {
    return x > 0.f ? x : x * s;
}

__device__ __forceinline__ void atomicMaxF(float* addr, float v) {
    if (v >= 0.f) atomicMax((int*)addr, __float_as_int(v));
    else          atomicMin((unsigned int*)addr, __float_as_uint(v));
}

// ---------------- init ----------------
__global__ void k_init() {
    int i = blockIdx.x * 256 + threadIdx.x;
    const float NEG_INF = __int_as_float(0xff800000);
    if (i < NN) g_deg[i] = 0;
    if (i < GG * 16) { g_gsum[i] = 0.f; g_gmax[i] = NEG_INF; }
    if (i < GG) g_npg[i] = 0.f;
}

// ---------------- x -> fp16 hi/lo split ----------------
__global__ void k_cvt(const float* __restrict__ x) {
    int i = blockIdx.x * 256 + threadIdx.x;  // i < NN*64/4
    if (i >= NN * 16) return;
    float4 v = *(const float4*)&x[i * 4];
    __half h0 = __float2half_rn(v.x), h1 = __float2half_rn(v.y);
    __half h2 = __float2half_rn(v.z), h3 = __float2half_rn(v.w);
    __half l0 = __float2half_rn(v.x - __half2float(h0));
    __half l1 = __float2half_rn(v.y - __half2float(h1));
    __half l2 = __float2half_rn(v.z - __half2float(h2));
    __half l3 = __float2half_rn(v.w - __half2float(h3));
    __half2 ha = __halves2half2(h0, h1), hb = __halves2half2(h2, h3);
    __half2 la = __halves2half2(l0, l1), lb = __halves2half2(l2, l3);
    uint2 uh, ul;
    uh.x = *(unsigned*)&ha; uh.y = *(unsigned*)&hb;
    ul.x = *(unsigned*)&la; ul.y = *(unsigned*)&lb;
    *(uint2*)&g_xh_hi[i * 4] = uh;
    *(uint2*)&g_xh_lo[i * 4] = ul;
}

// ---------------- pack weights: w1 hi/lo fp16, wh (gat_w + att cols) hi/lo, w2 fp32 ----------------
__global__ void k_pack(const float* __restrict__ rw1, const float* __restrict__ root1,
                       const float* __restrict__ rw2, const float* __restrict__ root2,
                       const float* __restrict__ gat_w, const float* __restrict__ att_src,
                       const float* __restrict__ att_dst) {
    int i = blockIdx.x * 256 + threadIdx.x;
    if (i < 64 * 288) {
        int k = i / 288, j = i % 288;
        float v = (j < 256) ? rw1[((j >> 5) * 64 + k) * 32 + (j & 31)]
                            : root1[k * 32 + (j - 256)];
        __half h = __float2half_rn(v);
        g_w1h[i] = h;
        g_w1l[i] = __float2half_rn(v - __half2float(h));
    } else if (i < 64 * 288 + 64 * 144) {
        int t = i - 64 * 288;
        int k = t / 144, j = t % 144;
        float v = 0.f;
        if (j < 128) {
            v = gat_w[k * 128 + j];
        } else if (j < 132) {
            int head = j - 128;
            for (int c = 0; c < 32; c++)
                v += gat_w[k * 128 + head * 32 + c] * att_src[head * 32 + c];
        } else if (j < 136) {
            int head = j - 132;
            for (int c = 0; c < 32; c++)
                v += gat_w[k * 128 + head * 32 + c] * att_dst[head * 32 + c];
        }
        __half h = __float2half_rn(v);
        g_whh[t] = h;
        g_whl[t] = __float2half_rn(v - __half2float(h));
    } else if (i < 64 * 288 + 64 * 144 + 32 * 144) {
        int t = i - 64 * 288 - 64 * 144;
        int k = t / 144, j = t % 144;
        g_w2[t] = (j < 128) ? rw2[((j >> 4) * 32 + k) * 16 + (j & 15)]
                            : root2[k * 16 + (j - 128)];
    }
}

// ---------------- CSR build ----------------
__global__ void k_count(const int* __restrict__ dst) {
    int e = blockIdx.x * 256 + threadIdx.x;
    atomicAdd(&g_deg[dst[e]], 1);
}

__global__ void k_scan1() {
    __shared__ int s[1024];
    int t = threadIdx.x;
    int i = blockIdx.x * 1024 + t;
    int v = (i < NN) ? g_deg[i] : 0;
    s[t] = v;
    __syncthreads();
    for (int ofs = 1; ofs < 1024; ofs <<= 1) {
        int add = (t >= ofs) ? s[t - ofs] : 0;
        __syncthreads();
        s[t] += add;
        __syncthreads();
    }
    g_scan[i] = s[t];
    if (t == 1023) g_bsum[blockIdx.x] = s[1023];
}

__global__ void k_scan2() {
    if (threadIdx.x == 0) {
        int run = 0;
        for (int b = 0; b < NBLK; b++) { g_bpre[b] = run; run += g_bsum[b]; }
    }
}

__global__ void k_scan3() {
    int i = blockIdx.x * 1024 + threadIdx.x;
    if (i < NN) {
        int excl = g_scan[i] - g_deg[i] + g_bpre[blockIdx.x];
        g_off[i] = excl;
        g_cur[i] = excl;
    }
}

__global__ void k_scatter(const int* __restrict__ src, const int* __restrict__ dst,
                          const int* __restrict__ et) {
    int e = blockIdx.x * 256 + threadIdx.x;
    int d = dst[e];
    int p = atomicAdd(&g_cur[d], 1);
    g_csr[p] = src[e] | (et[e] << 20);
}

// ---------------- tensor-core GEMM: C[N, OC] = A[N,64] @ B[64,OC], split fp16, fp32 accum ----------------
// 4 warps, block covers 64 rows. IS_H: OC=144 logical, cols 0..127 -> g_hh (stride 128),
// cols 128..135 -> g_asrc/g_adst fp32, rest dropped.
template<int OC, bool IS_H>
__global__ void __launch_bounds__(128)
k_wmma(const __half* __restrict__ Bhi, const __half* __restrict__ Blo,
       __half* __restrict__ C) {
    constexpr int LDA = 72;
    __shared__ __half sAh[64 * LDA];
    __shared__ __half sAl[64 * LDA];
    __shared__ float stage[4][256];
    const int n0 = blockIdx.x * 64;
    const int tid = threadIdx.x;
    const int w = tid >> 5, lane = tid & 31;

    for (int i = tid; i < 64 * 8; i += 128) {   // uint4 = 8 halves per chunk
        int r = i >> 3, cc = (i & 7) * 8;
        int n = n0 + r;
        uint4 vh = make_uint4(0, 0, 0, 0), vl = make_uint4(0, 0, 0, 0);
        if (n < NN) {
            vh = *(const uint4*)&g_xh_hi[n * 64 + cc];
            vl = *(const uint4*)&g_xh_lo[n * 64 + cc];
        }
        *(uint4*)&sAh[r * LDA + cc] = vh;
        *(uint4*)&sAl[r * LDA + cc] = vl;
    }
    __syncthreads();

    wmma::fragment<wmma::matrix_a, 16, 16, 16, __half, wmma::row_major> ah[4], al[4];
#pragma unroll
    for (int kt = 0; kt < 4; kt++) {
        wmma::load_matrix_sync(ah[kt], &sAh[w * 16 * LDA + kt * 16], LDA);
        wmma::load_matrix_sync(al[kt], &sAl[w * 16 * LDA + kt * 16], LDA);
    }

    for (int ct = 0; ct < OC / 16; ct++) {
        wmma::fragment<wmma::accumulator, 16, 16, 16, float> acc;
        wmma::fill_fragment(acc, 0.f);
#pragma unroll
        for (int kt = 0; kt < 4; kt++) {
            wmma::fragment<wmma::matrix_b, 16, 16, 16, __half, wmma::row_major> bh, bl;
            wmma::load_matrix_sync(bh, &Bhi[kt * 16 * OC + ct * 16], OC);
            wmma::load_matrix_sync(bl, &Blo[kt * 16 * OC + ct * 16], OC);
            wmma::mma_sync(acc, ah[kt], bh, acc);
            wmma::mma_sync(acc, ah[kt], bl, acc);
            wmma::mma_sync(acc, al[kt], bh, acc);
        }
        wmma::store_matrix_sync(stage[w], acc, 16, wmma::mem_row_major);
        __syncwarp();
        if (!IS_H) {
            for (int idx = lane; idx < 128; idx += 32) {
                int r = idx >> 3, c2 = idx & 7;
                int n = n0 + w * 16 + r;
                if (n < NN) {
                    __half2 hv = __floats2half2_rn(stage[w][r * 16 + c2 * 2],
                                                   stage[w][r * 16 + c2 * 2 + 1]);
                    *(__half2*)&C[n * OC + ct * 16 + c2 * 2] = hv;
                }
            }
        } else if (ct < 8) {
            for (int idx = lane; idx < 128; idx += 32) {
                int r = idx >> 3, c2 = idx & 7;
                int n = n0 + w * 16 + r;
                if (n < NN) {
                    __half2 hv = __floats2half2_rn(stage[w][r * 16 + c2 * 2],
                                                   stage[w][r * 16 + c2 * 2 + 1]);
                    *(__half2*)&C[n * 128 + ct * 16 + c2 * 2] = hv;
                }
            }
        } else {
            for (int idx = lane; idx < 256; idx += 32) {
                int r = idx >> 4, c = idx & 15;
                int n = n0 + w * 16 + r;
                if (n < NN) {
                    float v = stage[w][r * 16 + c];
                    if (c < 4) g_asrc[n * 4 + c] = v;
                    else if (c < 8) g_adst[n * 4 + c - 4] = v;
                }
            }
        }
        __syncwarp();
    }
}

// ---------------- SIMT smem GEMM (kept for xw2): C[N, OC_TOTAL] = A[N, IC] @ W[IC, OC_TOTAL], fp16 out ----------------
template<int IC, int OC_TOTAL, int OC_CHUNK, int NPB, int TN, int TC>
__global__ void __launch_bounds__((NPB / TN) * (OC_CHUNK / TC))
k_gemm(const float* __restrict__ A, const float* __restrict__ W, __half* __restrict__ C,
       int nbase) {
    constexpr int THREADS = (NPB / TN) * (OC_CHUNK / TC);
    __shared__ float ws[IC * OC_CHUNK];
    __shared__ float xs[NPB * IC];
    const int col0 = blockIdx.y * OC_CHUNK;

    for (int i = threadIdx.x; i < IC * OC_CHUNK / 4; i += THREADS) {
        int k = (i * 4) / OC_CHUNK, j = (i * 4) % OC_CHUNK;
        *(float4*)&ws[i * 4] = *(const float4*)&W[k * OC_TOTAL + col0 + j];
    }
    const int n0 = nbase + blockIdx.x * NPB;
    for (int i = threadIdx.x; i < NPB * IC / 4; i += THREADS) {
        int r = (i * 4) / IC, k = (i * 4) % IC;
        int n = n0 + r;
        float4 v = make_float4(0.f, 0.f, 0.f, 0.f);
        if (n < NN) v = *(const float4*)&A[n * IC + k];
        *(float4*)&xs[i * 4] = v;
    }
    __syncthreads();

    const int tc = threadIdx.x % (OC_CHUNK / TC);
    const int tn = threadIdx.x / (OC_CHUNK / TC);
    float acc[TN][TC];
#pragma unroll
    for (int i = 0; i < TN; i++)
#pragma unroll
        for (int j = 0; j < TC; j++) acc[i][j] = 0.f;

    const float* xb = &xs[tn * TN * IC];
    const float* wb = &ws[tc * TC];
    for (int k4 = 0; k4 < IC / 4; k4++) {
        float4 xv[TN];
#pragma unroll
        for (int i = 0; i < TN; i++) xv[i] = *(const float4*)&xb[i * IC + k4 * 4];
#pragma unroll
        for (int kk = 0; kk < 4; kk++) {
            float wr[TC];
#pragma unroll
            for (int j4 = 0; j4 < TC / 4; j4++)
                *(float4*)&wr[j4 * 4] = *(const float4*)&wb[(k4 * 4 + kk) * OC_CHUNK + j4 * 4];
#pragma unroll
            for (int i = 0; i < TN; i++) {
                float xvk = (kk == 0) ? xv[i].x : (kk == 1) ? xv[i].y : (kk == 2) ? xv[i].z : xv[i].w;
#pragma unroll
                for (int j = 0; j < TC; j++) acc[i][j] = fmaf(xvk, wr[j], acc[i][j]);
            }
        }
    }
#pragma unroll
    for (int i = 0; i < TN; i++) {
        int n = n0 + tn * TN + i;
        if (n < NN) {
#pragma unroll
            for (int j4 = 0; j4 < TC / 4; j4++) {
                __half2 h0 = __floats2half2_rn(acc[i][j4 * 4 + 0], acc[i][j4 * 4 + 1]);
                __half2 h1 = __floats2half2_rn(acc[i][j4 * 4 + 2], acc[i][j4 * 4 + 3]);
                uint2 u;
                u.x = *(unsigned*)&h0;
                u.y = *(unsigned*)&h1;
                *(uint2*)&C[n * OC_TOTAL + col0 + tc * TC + j4 * 4] = u;
            }
        }
    }
}

// ---------------- fused GAT: dual-edge softmax-free aggregate + dense1 + graph max pool ----------------
__global__ void __launch_bounds__(256) k_gat(const float* __restrict__ gat_bias,
                                             const float* __restrict__ d1w,
                                             const float* __restrict__ d1b,
                                             const int* __restrict__ batch) {
    __shared__ float ws[128 * 16];
    __shared__ float sb[16];
    __shared__ float sbias[128];
    __shared__ float stage[8][128];
    for (int i = threadIdx.x; i < 2048; i += 256) ws[i] = d1w[i];
    if (threadIdx.x < 16) sb[threadIdx.x] = d1b[threadIdx.x];
    if (threadIdx.x < 128) sbias[threadIdx.x] = gat_bias[threadIdx.x];
    __syncthreads();

    int w = threadIdx.x >> 5, lane = threadIdx.x & 31;
    int d = blockIdx.x * 8 + w;
    int base = g_off[d], deg = g_deg[d];
    int hd = lane >> 3;
    float adh = g_adst[d * 4 + hd];

    float psum = 0.f;
    float4 acc0 = make_float4(0.f, 0.f, 0.f, 0.f);
    float4 acc1 = make_float4(0.f, 0.f, 0.f, 0.f);
    for (int j0 = 0; j0 < deg; j0 += 32) {
        int pk = (j0 + lane < deg) ? g_csr[base + j0 + lane] : 0;
        int m = min(32, deg - j0);
        int jj = 0;
        for (; jj + 1 < m; jj += 2) {
            int pk0 = __shfl_sync(0xFFFFFFFF, pk, jj);
            int pk1 = __shfl_sync(0xFFFFFFFF, pk, jj + 1);
            int s0 = pk0 & 0xFFFFF, s1 = pk1 & 0xFFFFF;
            float a0 = g_asrc[s0 * 4 + hd];
            float a1 = g_asrc[s1 * 4 + hd];
            float p0 = __expf(lrelu(a0 + adh, 0.2f));
            float p1 = __expf(lrelu(a1 + adh, 0.2f));
            uint2 u0 = *(const uint2*)&g_hh[s0 * 128 + lane * 4];
            uint2 u1 = *(const uint2*)&g_hh[s1 * 128 + lane * 4];
            float2 h0a = __half22float2(*(__half2*)&u0.x);
            float2 h0b = __half22float2(*(__half2*)&u0.y);
            float2 h1a = __half22float2(*(__half2*)&u1.x);
            float2 h1b = __half22float2(*(__half2*)&u1.y);
            psum += p0 + p1;
            acc0.x = fmaf(h0a.x, p0, acc0.x); acc1.x = fmaf(h1a.x, p1, acc1.x);
            acc0.y = fmaf(h0a.y, p0, acc0.y); acc1.y = fmaf(h1a.y, p1, acc1.y);
            acc0.z = fmaf(h0b.x, p0, acc0.z); acc1.z = fmaf(h1b.x, p1, acc1.z);
            acc0.w = fmaf(h0b.y, p0, acc0.w); acc1.w = fmaf(h1b.y, p1, acc1.w);
        }
        if (jj < m) {
            int pk0 = __shfl_sync(0xFFFFFFFF, pk, jj);
            int s0 = pk0 & 0xFFFFF;
            float a0 = g_asrc[s0 * 4 + hd];
            float p0 = __expf(lrelu(a0 + adh, 0.2f));
            uint2 u0 = *(const uint2*)&g_hh[s0 * 128 + lane * 4];
            float2 h0a = __half22float2(*(__half2*)&u0.x);
            float2 h0b = __half22float2(*(__half2*)&u0.y);
            psum += p0;
            acc0.x = fmaf(h0a.x, p0, acc0.x);
            acc0.y = fmaf(h0a.y, p0, acc0.y);
            acc0.z = fmaf(h0b.x, p0, acc0.z);
            acc0.w = fmaf(h0b.y, p0, acc0.w);
        }
    }
    float4 acc = make_float4(acc0.x + acc1.x, acc0.y + acc1.y,
                             acc0.z + acc1.z, acc0.w + acc1.w);
    float rinv = (psum > 0.f) ? 1.f / psum : 0.f;
    stage[w][lane * 4 + 0] = lrelu(fmaf(acc.x, rinv, sbias[lane * 4 + 0]), 0.01f);
    stage[w][lane * 4 + 1] = lrelu(fmaf(acc.y, rinv, sbias[lane * 4 + 1]), 0.01f);
    stage[w][lane * 4 + 2] = lrelu(fmaf(acc.z, rinv, sbias[lane * 4 + 2]), 0.01f);
    stage[w][lane * 4 + 3] = lrelu(fmaf(acc.w, rinv, sbias[lane * 4 + 3]), 0.01f);
    __syncwarp();
    // dense1: j = lane&15, split-k over halves
    int j = lane & 15, half = lane >> 4;
    float o = (half == 0) ? sb[j] : 0.f;
    const float4* sr = (const float4*)&stage[w][half * 64];
#pragma unroll
    for (int k4 = 0; k4 < 16; k4++) {
        float4 av = sr[k4];
        int kb = half * 64 + k4 * 4;
        o = fmaf(av.x, ws[(kb + 0) * 16 + j], o);
        o = fmaf(av.y, ws[(kb + 1) * 16 + j], o);
        o = fmaf(av.z, ws[(kb + 2) * 16 + j], o);
        o = fmaf(av.w, ws[(kb + 3) * 16 + j], o);
    }
    o += __shfl_down_sync(0xFFFFFFFF, o, 16);
    if (lane < 16) {
        o = lrelu(o, 0.01f);
        atomicMaxF(&g_gmax[batch[d] * 16 + j], o);
    }
}

// ---------------- RGCN layer 1: quad-edge CSR aggregate + mean + root + relu -> z1 ----------------
__global__ void __launch_bounds__(256) k_rgcn1(const float* __restrict__ rb1, int dbase) {
    __shared__ float sinv[8][8];
    int w = threadIdx.x >> 5, lane = threadIdx.x & 31;
    int d = dbase + blockIdx.x * 8 + w;
    int base = g_off[d], deg = g_deg[d];
    int grp = lane >> 3, gl = lane & 7;

    int c0 = 0, c1 = 0, c2 = 0, c3 = 0, c4 = 0, c5 = 0, c6 = 0, c7 = 0;
    for (int i0 = 0; i0 < deg; i0 += 32) {
        int r = (i0 + lane < deg) ? ((g_csr[base + i0 + lane] >> 20) & 7) : 8;
        c0 += __popc(__ballot_sync(0xFFFFFFFF, r == 0));
        c1 += __popc(__ballot_sync(0xFFFFFFFF, r == 1));
        c2 += __popc(__ballot_sync(0xFFFFFFFF, r == 2));
        c3 += __popc(__ballot_sync(0xFFFFFFFF, r == 3));
        c4 += __popc(__ballot_sync(0xFFFFFFFF, r == 4));
        c5 += __popc(__ballot_sync(0xFFFFFFFF, r == 5));
        c6 += __popc(__ballot_sync(0xFFFFFFFF, r == 6));
        c7 += __popc(__ballot_sync(0xFFFFFFFF, r == 7));
    }
    if (lane < 8) {
        int cc = (lane == 0) ? c0 : (lane == 1) ? c1 : (lane == 2) ? c2 : (lane == 3) ? c3 :
                 (lane == 4) ? c4 : (lane == 5) ? c5 : (lane == 6) ? c6 : c7;
        sinv[w][lane] = cc ? 1.f / (float)cc : 0.f;
    }
    __syncwarp();

    float4 acc = make_float4(0.f, 0.f, 0.f, 0.f);
    for (int j0 = 0; j0 < deg; j0 += 32) {
        int pk = (j0 + lane < deg) ? g_csr[base + j0 + lane] : 0;
        int m = min(32, deg - j0);
        for (int jj = 0; jj < m; jj += 4) {
            int idx = jj + grp;
            bool ok = idx < m;
            int pkj = __shfl_sync(0xFFFFFFFF, pk, min(idx, 31));
            if (ok) {
                int s = pkj & 0xFFFFF, r = (pkj >> 20) & 7;
                float inv = sinv[w][r];
                uint2 u = *(const uint2*)&g_xw1[s * 288 + r * 32 + gl * 4];
                float2 va = __half22float2(*(__half2*)&u.x);
                float2 vb = __half22float2(*(__half2*)&u.y);
                acc.x = fmaf(va.x, inv, acc.x);
                acc.y = fmaf(va.y, inv, acc.y);
                acc.z = fmaf(vb.x, inv, acc.z);
                acc.w = fmaf(vb.y, inv, acc.w);
            }
        }
    }
    acc.x += __shfl_down_sync(0xFFFFFFFF, acc.x, 16);
    acc.y += __shfl_down_sync(0xFFFFFFFF, acc.y, 16);
    acc.z += __shfl_down_sync(0xFFFFFFFF, acc.z, 16);
    acc.w += __shfl_down_sync(0xFFFFFFFF, acc.w, 16);
    acc.x += __shfl_down_sync(0xFFFFFFFF, acc.x, 8);
    acc.y += __shfl_down_sync(0xFFFFFFFF, acc.y, 8);
    acc.z += __shfl_down_sync(0xFFFFFFFF, acc.z, 8);
    acc.w += __shfl_down_sync(0xFFFFFFFF, acc.w, 8);
    if (lane < 8) {
        uint2 u = *(const uint2*)&g_xw1[d * 288 + 256 + gl * 4];
        float2 ra = __half22float2(*(__half2*)&u.x);
        float2 rb = __half22float2(*(__half2*)&u.y);
        float4 b = *(const float4*)&rb1[gl * 4];
        float4 o;
        o.x = fmaxf(acc.x + ra.x + b.x, 0.f);
        o.y = fmaxf(acc.y + ra.y + b.y, 0.f);
        o.z = fmaxf(acc.z + rb.x + b.z, 0.f);
        o.w = fmaxf(acc.w + rb.y + b.w, 0.f);
        *(float4*)&g_z1[d * 32 + gl * 4] = o;
    }
}

// ---------------- RGCN layer 2: quad-edge CSR aggregate + mean + root + relu + graph sum pool ----------------
__global__ void __launch_bounds__(256) k_rgcn2(const float* __restrict__ rb2,
                                               const int* __restrict__ batch) {
    __shared__ float sinv[8][8];
    int w = threadIdx.x >> 5, lane = threadIdx.x & 31;
    int d = blockIdx.x * 8 + w;
    int base = g_off[d], deg = g_deg[d];
    int grp = lane >> 3, gl = lane & 7;

    int c0 = 0, c1 = 0, c2 = 0, c3 = 0, c4 = 0, c5 = 0, c6 = 0, c7 = 0;
    for (int i0 = 0; i0 < deg; i0 += 32) {
        int r = (i0 + lane < deg) ? ((g_csr[base + i0 + lane] >> 20) & 7) : 8;
        c0 += __popc(__ballot_sync(0xFFFFFFFF, r == 0));
        c1 += __popc(__ballot_sync(0xFFFFFFFF, r == 1));
        c2 += __popc(__ballot_sync(0xFFFFFFFF, r == 2));
        c3 += __popc(__ballot_sync(0xFFFFFFFF, r == 3));
        c4 += __popc(__ballot_sync(0xFFFFFFFF, r == 4));
        c5 += __popc(__ballot_sync(0xFFFFFFFF, r == 5));
        c6 += __popc(__ballot_sync(0xFFFFFFFF, r == 6));
        c7 += __popc(__ballot_sync(0xFFFFFFFF, r == 7));
    }
    if (lane < 8) {
        int cc = (lane == 0) ? c0 : (lane == 1) ? c1 : (lane == 2) ? c2 : (lane == 3) ? c3 :
                 (lane == 4) ? c4 : (lane == 5) ? c5 : (lane == 6) ? c6 : c7;
        sinv[w][lane] = cc ? 1.f / (float)cc : 0.f;
    }
    __syncwarp();

    float2 acc = make_float2(0.f, 0.f);
    for (int j0 = 0; j0 < deg; j0 += 32) {
        int pk = (j0 + lane < deg) ? g_csr[base + j0 + lane] : 0;
        int m = min(32, deg - j0);
        for (int jj = 0; jj < m; jj += 4) {
            int idx = jj + grp;
            bool ok = idx < m;
            int pkj = __shfl_sync(0xFFFFFFFF, pk, min(idx, 31));
            if (ok) {
                int s = pkj & 0xFFFFF, r = (pkj >> 20) & 7;
                float inv = sinv[w][r];
                unsigned u = *(const unsigned*)&g_xw2[s * 144 + r * 16 + gl * 2];
                float2 v = __half22float2(*(__half2*)&u);
                acc.x = fmaf(v.x, inv, acc.x);
                acc.y = fmaf(v.y, inv, acc.y);
            }
        }
    }
    acc.x += __shfl_down_sync(0xFFFFFFFF, acc.x, 16);
    acc.y += __shfl_down_sync(0xFFFFFFFF, acc.y, 16);
    acc.x += __shfl_down_sync(0xFFFFFFFF, acc.x, 8);
    acc.y += __shfl_down_sync(0xFFFFFFFF, acc.y, 8);
    if (lane < 8) {
        unsigned u = *(const unsigned*)&g_xw2[d * 144 + 128 + gl * 2];
        float2 root = __half22float2(*(__half2*)&u);
        float2 b = *(const float2*)&rb2[gl * 2];
        float zx = fmaxf(acc.x + root.x + b.x, 0.f);
        float zy = fmaxf(acc.y + root.y + b.y, 0.f);
        int g = batch[d];
        atomicAdd(&g_gsum[g * 16 + gl * 2 + 0], zx);
        atomicAdd(&g_gsum[g * 16 + gl * 2 + 1], zy);
        if (lane == 0) atomicAdd(&g_npg[g], 1.f);
    }
}

// ---------------- final readout ----------------
__global__ void k_final(const float* __restrict__ dw, const float* __restrict__ db,
                        float* __restrict__ out) {
    int g = threadIdx.x;
    float inv = 1.f / g_npg[g];
    float acc = db[0];
#pragma unroll
    for (int c = 0; c < 16; c++) {
        acc = fmaf(g_gmax[g * 16 + c], dw[c], acc);
        acc = fmaf(g_gsum[g * 16 + c] * inv, dw[16 + c], acc);
    }
    out[g] = acc;
}

// ---------------- launch ----------------
extern "C" void kernel_launch(void* const* d_in, const int* in_sizes, int n_in,
                              void* d_out, int out_size) {
    const float* x        = (const float*)d_in[0];
    const int*   ei       = (const int*)d_in[1];
    const int*   et       = (const int*)d_in[2];
    const int*   batch    = (const int*)d_in[3];
    const float* gat_w    = (const float*)d_in[4];
    const float* att_src  = (const float*)d_in[5];
    const float* att_dst  = (const float*)d_in[6];
    const float* gat_bias = (const float*)d_in[7];
    const float* d1w      = (const float*)d_in[8];
    const float* d1b      = (const float*)d_in[9];
    const float* rw1      = (const float*)d_in[10];
    const float* root1    = (const float*)d_in[11];
    const float* rb1      = (const float*)d_in[12];
    const float* rw2      = (const float*)d_in[13];
    const float* root2    = (const float*)d_in[14];
    const float* rb2      = (const float*)d_in[15];
    const float* dw       = (const float*)d_in[16];
    const float* db       = (const float*)d_in[17];
    float* out = (float*)d_out;

    const int* src = ei;
    const int* dst = ei + EE;

    void *p_w1h, *p_w1l, *p_whh, *p_whl, *p_w2, *p_xw1, *p_xw2, *p_z1, *p_hh;
    cudaGetSymbolAddress(&p_w1h, g_w1h);
    cudaGetSymbolAddress(&p_w1l, g_w1l);
    cudaGetSymbolAddress(&p_whh, g_whh);
    cudaGetSymbolAddress(&p_whl, g_whl);
    cudaGetSymbolAddress(&p_w2, g_w2);
    cudaGetSymbolAddress(&p_xw1, g_xw1);
    cudaGetSymbolAddress(&p_xw2, g_xw2);
    cudaGetSymbolAddress(&p_z1, g_z1);
    cudaGetSymbolAddress(&p_hh, g_hh);

    cudaStream_t s2 = g_fork.s2;
    cudaStream_t s3 = g_fork.s3;

    cudaEventRecord(g_fork.evStart, 0);
    cudaStreamWaitEvent(s2, g_fork.evStart, 0);
    cudaStreamWaitEvent(s3, g_fork.evStart, 0);

    // s2: init + CSR build
    k_init<<<(NN + 255) / 256, 256, 0, s2>>>();
    k_count<<<EE / 256, 256, 0, s2>>>(dst);
    k_scan1<<<NBLK, 1024, 0, s2>>>();
    k_scan2<<<1, 32, 0, s2>>>();
    k_scan3<<<NBLK, 1024, 0, s2>>>();
    k_scatter<<<EE / 256, 256, 0, s2>>>(src, dst, et);
    cudaEventRecord(g_fork.evCSR, s2);

    // s3: x fp16 split
    k_cvt<<<(NN * 16 + 255) / 256, 256, 0, s3>>>(x);
    cudaEventRecord(g_fork.evCvt, s3);

    // main: pack weights
    k_pack<<<(64 * 288 + 64 * 144 + 32 * 144 + 255) / 256, 256>>>(
        rw1, root1, rw2, root2, gat_w, att_src, att_dst);
    cudaEventRecord(g_fork.evPack, 0);

    // s3: h GEMM (tensor cores) + fused GAT after CSR
    cudaStreamWaitEvent(s3, g_fork.evPack, 0);
    k_wmma<144, true><<<(NN + 63) / 64, 128, 0, s3>>>(
        (const __half*)p_whh, (const __half*)p_whl, (__half*)p_hh);
    cudaStreamWaitEvent(s3, g_fork.evCSR, 0);
    k_gat<<<NN / 8, 256, 0, s3>>>(gat_bias, d1w, d1b, batch);
    cudaEventRecord(g_fork.evGat, s3);

    // main: xw1 GEMM (tensor cores)
    cudaStreamWaitEvent(0, g_fork.evCvt, 0);
    k_wmma<288, false><<<(NN + 63) / 64, 128>>>(
        (const __half*)p_w1h, (const __half*)p_w1l, (__half*)p_xw1);
    cudaStreamWaitEvent(0, g_fork.evCSR, 0);

    // pipelined rgcn1 / xw2 halves
    k_rgcn1<<<SPLIT / 8, 256>>>(rb1, 0);
    cudaEventRecord(g_fork.evR1, 0);
    k_rgcn1<<<(NN - SPLIT) / 8, 256>>>(rb1, SPLIT);

    cudaStreamWaitEvent(s2, g_fork.evR1, 0);
    k_gemm<32, 144, 144, 64, 8, 8><<<dim3(SPLIT / 64, 1), 144, 0, s2>>>(
        (const float*)p_z1, (const float*)p_w2, (__half*)p_xw2, 0);
    cudaEventRecord(g_fork.evX2lo, s2);

    k_gemm<32, 144, 144, 64, 8, 8><<<dim3((NN - SPLIT + 63) / 64, 1), 144>>>(
        (const float*)p_z1, (const float*)p_w2, (__half*)p_xw2, SPLIT);
    cudaStreamWaitEvent(0, g_fork.evX2lo, 0);
    k_rgcn2<<<NN / 8, 256>>>(rb2, batch);

    cudaStreamWaitEvent(0, g_fork.evGat, 0);
    k_final<<<1, 256>>>(dw, db, out);
}